// round 14
// baseline (speedup 1.0000x reference)
#include <cuda_runtime.h>
#include <math.h>
#include <stdint.h>

#define SEQ 1024
#define BATCH 8
#define MTOT (BATCH*SEQ)   // 8192
#define NHEADS 8
#define DHEAD 64
#define DMODEL 512
#define DIN 524
#define DFF 2048
#define NCLS 1024
#define OUTROW 1036

// ---------------- scratch (device globals; no allocation allowed) ----------------
__device__ float g_x [MTOT*DIN];
__device__ float g_h [MTOT*DMODEL];
__device__ float g_hn[MTOT*DMODEL];
__device__ float g_q [MTOT*DMODEL];
__device__ float g_k [MTOT*DMODEL];
__device__ float g_v [MTOT*DMODEL];
__device__ float g_o [MTOT*DMODEL];
__device__ float g_ff[MTOT*DFF];
__device__ float g_out2[MTOT*DIN];
__device__ float g_bias[NHEADS*SEQ];

// transposed + tf32-pre-rounded weight storage: layout [N][K]
#define SZ_PIN  (DIN*DMODEL)
#define SZ_W    (DMODEL*DMODEL)
#define SZ_W1   (DMODEL*DFF)
#define SZ_POUT (DMODEL*DIN)
#define SZ_CLS  (DMODEL*NCLS)
#define OFF_PIN  0
#define OFF_WQ   (OFF_PIN + SZ_PIN)
#define OFF_WK   (OFF_WQ + 6*SZ_W)
#define OFF_WV   (OFF_WK + 6*SZ_W)
#define OFF_WO   (OFF_WV + 6*SZ_W)
#define OFF_W1   (OFF_WO + 6*SZ_W)
#define OFF_W2   (OFF_W1 + 6*SZ_W1)
#define OFF_POUT (OFF_W2 + 6*SZ_W1)
#define OFF_CLS  (OFF_POUT + SZ_POUT)
#define WT_TOTAL (OFF_CLS + SZ_CLS)
__device__ float g_wt[WT_TOTAL];

// ---------------- tf32 helpers ----------------
__device__ __forceinline__ uint32_t f2tf32(float f) {
    uint32_t r;
    asm("cvt.rna.tf32.f32 %0, %1;" : "=r"(r) : "f"(f));
    return r;
}
__device__ __forceinline__ float tf32r(float f) {
    return __uint_as_float(f2tf32(f));
}
__device__ __forceinline__ void mma_tf32(float* c,
    uint32_t a0, uint32_t a1, uint32_t a2, uint32_t a3,
    uint32_t b0, uint32_t b1)
{
    asm volatile(
        "mma.sync.aligned.m16n8k8.row.col.f32.tf32.tf32.f32 "
        "{%0,%1,%2,%3}, {%4,%5,%6,%7}, {%8,%9}, {%0,%1,%2,%3};"
        : "+f"(c[0]), "+f"(c[1]), "+f"(c[2]), "+f"(c[3])
        : "r"(a0), "r"(a1), "r"(a2), "r"(a3), "r"(b0), "r"(b1));
}
__device__ __forceinline__ void ldmatrix_x4(uint32_t& r0, uint32_t& r1,
                                            uint32_t& r2, uint32_t& r3,
                                            uint32_t saddr)
{
    asm volatile("ldmatrix.sync.aligned.m8n8.x4.shared.b16 {%0,%1,%2,%3}, [%4];"
                 : "=r"(r0), "=r"(r1), "=r"(r2), "=r"(r3) : "r"(saddr));
}
__device__ __forceinline__ void cp_async16(float* dst, const float* src, bool pred) {
    uint32_t d = (uint32_t)__cvta_generic_to_shared(dst);
    int bytes = pred ? 16 : 0;
    asm volatile("cp.async.cg.shared.global [%0], [%1], 16, %2;\n"
                 :: "r"(d), "l"(src), "r"(bytes));
}
__device__ __forceinline__ void cp_commit() {
    asm volatile("cp.async.commit_group;\n" ::);
}
template<int N>
__device__ __forceinline__ void cp_wait() {
    asm volatile("cp.async.wait_group %0;\n" :: "n"(N));
}

// ---------------- weight transpose + tf32 round: src[K][N] -> dst[N][K] ----------------
__global__ __launch_bounds__(256)
void transpose_round_kernel(const float* __restrict__ src, float* __restrict__ dst,
                            int K, int N)
{
    __shared__ float tile[32][33];
    long off = (long)blockIdx.z * K * N;
    src += off; dst += off;
    int tx = threadIdx.x & 31, ty = threadIdx.x >> 5;
    int kb = blockIdx.y*32, nb = blockIdx.x*32;
    #pragma unroll
    for (int j = 0; j < 32; j += 8) {
        int k = kb + ty + j, n = nb + tx;
        tile[ty+j][tx] = (k < K && n < N) ? src[(long)k*N + n] : 0.f;
    }
    __syncthreads();
    #pragma unroll
    for (int j = 0; j < 32; j += 8) {
        int n = nb + ty + j, k = kb + tx;
        if (n < N && k < K) dst[(long)n*K + k] = tf32r(tile[tx][ty+j]);
    }
}

// ---------------- relpos bias table ----------------
__global__ void bias_table_kernel(const float* __restrict__ relpos)
{
    int n = blockIdx.x * blockDim.x + threadIdx.x;
    if (n >= SEQ) return;
    int bucket;
    if (n < 4) {
        bucket = n;
    } else {
        int vl = 4 + (int)(logf((float)n * 0.25f) * (4.0f / logf(8.0f)));
        bucket = vl < 7 ? vl : 7;
    }
    for (int h = 0; h < NHEADS; h++)
        g_bias[h*SEQ + n] = relpos[bucket*NHEADS + h] * 8.0f;  // * DIM_HEAD**0.5
}

// ---------------- embedding gather + concat (stores tf32-rounded) ----------------
__global__ __launch_bounds__(256)
void embed_kernel(const float* __restrict__ saml, const float* __restrict__ emb)
{
    int m = blockIdx.x;
    int b = m >> 10, s = m & 1023;
    const float* row = saml + ((long)b*1025 + s)*13;
    int id = (int)row[0];
    float* x = g_x + (long)m*DIN;
    const float* erow = emb + (long)id*512;
    for (int c = threadIdx.x; c < DIN; c += 256)
        x[c] = tf32r((c < 512) ? erow[c] : row[c - 511]);
}

// ---------------- TF32 tensor-core GEMM body ----------------
// 2-stage cp.async; A [M][K], Bt [N][K] (transposed weights); ldmatrix for BOTH fragments.
// Epilogue staged through smem. TAILM: cols >= 512 go directly to Tout.
#define LDA_S 36
#define ASTG (128*LDA_S)
#define GEMM_SMEM ((4*ASTG)*4)     // 2 stages x (A + Bt), each 128x36
#define STG_LD 132

template<int MODE, bool TSTORE, bool ROT, int RND, int TAILM>
__device__ __forceinline__
void gemm_body(int M, int N, int K,
               const float* __restrict__ A, int lda,
               const float* __restrict__ Bt,
               const float* __restrict__ bias,
               const float* __restrict__ Res, int ldr,
               float* __restrict__ C, int ldc,
               float* __restrict__ Tout,
               int row0, int col0, float* sm)
{
    float* As = sm;
    float* Bs = sm + 2*ASTG;

    const int tid  = threadIdx.x;
    const int wid  = tid >> 5;
    const int lane = tid & 31;
    const int g    = lane >> 2;
    const int tg   = lane & 3;
    const int wm   = wid >> 2;
    const int wn   = wid & 3;

    const int l8 = lane & 7;
    const int lf8 = ((lane >> 3) & 1) * 8;
    const int lk4 = (lane >> 4) * 4;
    const uint32_t a_sbase = (uint32_t)__cvta_generic_to_shared(As)
        + (uint32_t)(((wm*64 + l8 + lf8)*LDA_S + lk4) * 4);
    const uint32_t b_sbase = (uint32_t)__cvta_generic_to_shared(Bs)
        + (uint32_t)(((wn*32 + l8 + lf8)*LDA_S + lk4) * 4);

    float acc[4][4][4];
    #pragma unroll
    for (int mi=0;mi<4;mi++)
        #pragma unroll
        for (int ni=0;ni<4;ni++)
            #pragma unroll
            for (int r=0;r<4;r++) acc[mi][ni][r]=0.f;

    const int nt = (K + 31) / 32;

#define LOAD_TILE(STG, KT)                                                        \
    {                                                                             \
        _Pragma("unroll")                                                         \
        for (int i = 0; i < 4; i++) {                                             \
            int idx = tid + i*256;                                                \
            int r  = idx >> 3;                                                    \
            int c4 = (idx & 7) * 4;                                               \
            int k4 = (KT) + c4;                                                   \
            bool p = (k4 < K);                                                    \
            const float* src = A + (long)(row0 + r)*lda + (p ? k4 : 0);           \
            cp_async16(As + (STG)*ASTG + r*LDA_S + c4, src, p);                   \
        }                                                                         \
        _Pragma("unroll")                                                         \
        for (int i = 0; i < 4; i++) {                                             \
            int idx = tid + i*256;                                                \
            int r  = idx >> 3;                                                    \
            int c4 = (idx & 7) * 4;                                               \
            int k4 = (KT) + c4;                                                   \
            int n  = col0 + r;                                                    \
            bool p = (k4 < K) && (n < N);                                         \
            const float* src = Bt + (long)(p ? n : 0)*K + (p ? k4 : 0);           \
            cp_async16(Bs + (STG)*ASTG + r*LDA_S + c4, src, p);                   \
        }                                                                         \
        cp_commit();                                                              \
    }

    LOAD_TILE(0, 0)

    for (int t = 0; t < nt; t++) {
        if (t + 1 < nt) {
            LOAD_TILE((t+1)&1, (t+1)*32)
            cp_wait<1>();
        } else {
            cp_wait<0>();
        }
        __syncthreads();

        const uint32_t a_st = a_sbase + (uint32_t)((t&1)*ASTG*4);
        const uint32_t b_st = b_sbase + (uint32_t)((t&1)*ASTG*4);
        #pragma unroll
        for (int ks = 0; ks < 4; ks++) {
            const int k8 = ks*8;
            uint32_t a[4][4], b[4][2];
            #pragma unroll
            for (int mi=0;mi<4;mi++)
                ldmatrix_x4(a[mi][0], a[mi][1], a[mi][2], a[mi][3],
                            a_st + (uint32_t)((mi*16*LDA_S + k8) * 4));
            #pragma unroll
            for (int pr=0;pr<2;pr++) {
                uint32_t r0_, r1_, r2_, r3_;
                ldmatrix_x4(r0_, r1_, r2_, r3_,
                            b_st + (uint32_t)((pr*16*LDA_S + k8) * 4));
                b[2*pr  ][0] = r0_; b[2*pr  ][1] = r2_;
                b[2*pr+1][0] = r1_; b[2*pr+1][1] = r3_;
            }
            #pragma unroll
            for (int mi=0;mi<4;mi++)
                #pragma unroll
                for (int ni=0;ni<4;ni++)
                    mma_tf32(acc[mi][ni], a[mi][0],a[mi][1],a[mi][2],a[mi][3],
                             b[ni][0], b[ni][1]);
        }
        __syncthreads();
    }
#undef LOAD_TILE

    // ---- rotary on accumulators (Q/K projections only) ----
    if (ROT && ((wn & 1) == 0)) {
        #pragma unroll
        for (int mi=0;mi<4;mi++) {
            #pragma unroll
            for (int r=0;r<4;r++) {
                int row = row0 + wm*64 + mi*16 + g + ((r>=2)?8:0);
                int s = row & 1023;
                #pragma unroll
                for (int ni=0;ni<2;ni++) {
                    int d = ni*8 + tg*2 + (r&1);
                    float inv = expf(-(float)(2*d) * (9.210340371976184f/32.f));
                    float ang = (float)s * inv;
                    float sn, c;
                    sincosf(ang, &sn, &c);
                    float a = acc[mi][ni][r];
                    float bb = acc[mi][ni+2][r];
                    acc[mi][ni  ][r] = a*c - bb*sn;
                    acc[mi][ni+2][r] = bb*c + a*sn;
                }
            }
        }
    }

    // ---- staged epilogue: two passes of 64 rows through smem ----
    float* stage = sm;
    #pragma unroll
    for (int p = 0; p < 2; p++) {
        __syncthreads();
        if (wm == p) {
            #pragma unroll
            for (int mi=0;mi<4;mi++)
                #pragma unroll
                for (int ni=0;ni<4;ni++)
                    #pragma unroll
                    for (int r=0;r<4;r++) {
                        int lr = mi*16 + g + ((r>=2)?8:0);
                        int lc = wn*32 + ni*8 + tg*2 + (r&1);
                        stage[lr*STG_LD + lc] = acc[mi][ni][r];
                    }
        }
        __syncthreads();
        if (TSTORE) {
            #pragma unroll
            for (int i = 0; i < 8; i++) {
                int idx = tid + i*256;
                int col = idx & 127;
                int r4  = (idx >> 7) * 4;
                int gcol = col0 + col;
                float o4[4];
                #pragma unroll
                for (int j = 0; j < 4; j++)
                    o4[j] = stage[(r4+j)*STG_LD + col] + bias[gcol];
                int b_ = row0 >> 10;
                int s_ = (row0 & 1023) + p*64 + r4;
                *(float4*)&C[(long)b_*(NCLS*OUTROW) + (long)gcol*OUTROW + s_] = *(float4*)o4;
            }
        } else {
            #pragma unroll
            for (int i = 0; i < 8; i++) {
                int idx = tid + i*256;
                int r  = idx >> 5;
                int c4 = (idx & 31) * 4;
                int row = row0 + p*64 + r;
                int col = col0 + c4;
                float4 v = *(float4*)&stage[r*STG_LD + c4];
                float vv[4] = {v.x, v.y, v.z, v.w};
                bool fastvec = (col + 3 < N) && (!TAILM || (col + 3 < 512));
                if (fastvec) {
                    if (MODE >= 1) {
                        float4 bb = *(const float4*)&bias[col];
                        vv[0]+=bb.x; vv[1]+=bb.y; vv[2]+=bb.z; vv[3]+=bb.w;
                    }
                    if (MODE == 2) {
                        float4 rr = *(const float4*)&Res[(long)row*ldr + col];
                        vv[0]+=rr.x; vv[1]+=rr.y; vv[2]+=rr.z; vv[3]+=rr.w;
                    }
                    #pragma unroll
                    for (int j = 0; j < 4; j++) {
                        float x = vv[j];
                        if (MODE == 3) x = 0.5f*x*(1.f + erff(x*0.7071067811865476f));
                        if (RND == 1) x = tf32r(x);
                        if (RND == 2 && col + j < 512) x = tf32r(x);
                        vv[j] = x;
                    }
                    *(float4*)&C[(long)row*ldc + col] = make_float4(vv[0],vv[1],vv[2],vv[3]);
                } else {
                    #pragma unroll
                    for (int j = 0; j < 4; j++) {
                        int cc = col + j;
                        if (cc < N) {
                            float x = vv[j];
                            if (MODE >= 1) x += bias[cc];
                            if (MODE == 2) x += Res[(long)row*ldr + cc];
                            if (MODE == 3) x = 0.5f*x*(1.f + erff(x*0.7071067811865476f));
                            if (TAILM && cc >= 512) {
                                int b_ = row >> 10, s_ = row & 1023;
                                Tout[(long)b_*(NCLS*OUTROW) + (long)s_*OUTROW + NCLS + (cc - 512)] = x;
                            } else {
                                if (RND == 1) x = tf32r(x);
                                if (RND == 2 && cc < 512) x = tf32r(x);
                                C[(long)row*ldc + cc] = x;
                            }
                        }
                    }
                }
            }
        }
    }
}

template<int MODE, bool TSTORE, int RND, int TAILM>
__global__ __launch_bounds__(256)
void tgemm_kernel(int M, int N, int K,
                  const float* __restrict__ A, int lda,
                  const float* __restrict__ Bt,
                  const float* __restrict__ bias,
                  const float* __restrict__ Res, int ldr,
                  float* __restrict__ C, int ldc,
                  float* __restrict__ Tout)
{
    extern __shared__ float sm[];
    gemm_body<MODE,TSTORE,false,RND,TAILM>(M, N, K, A, lda, Bt, bias, Res, ldr,
                                           C, ldc, Tout,
                                           blockIdx.y*128, blockIdx.x*128, sm);
}

// fused QKV with rotary on Q/K outputs: grid (12, 64)
__global__ __launch_bounds__(256)
void qkv_kernel(const float* __restrict__ A,
                const float* __restrict__ wq, const float* __restrict__ wk,
                const float* __restrict__ wv,
                float* __restrict__ q, float* __restrict__ k, float* __restrict__ v)
{
    extern __shared__ float sm[];
    int sel = blockIdx.x >> 2;
    int row0 = blockIdx.y*128, col0 = (blockIdx.x & 3)*128;
    if (sel == 0)
        gemm_body<0,false,true ,0,0>(MTOT, DMODEL, DMODEL, A, DMODEL, wq,
                                     nullptr, nullptr, 0, q, DMODEL, nullptr, row0, col0, sm);
    else if (sel == 1)
        gemm_body<0,false,true ,0,0>(MTOT, DMODEL, DMODEL, A, DMODEL, wk,
                                     nullptr, nullptr, 0, k, DMODEL, nullptr, row0, col0, sm);
    else
        gemm_body<0,false,false,0,0>(MTOT, DMODEL, DMODEL, A, DMODEL, wv,
                                     nullptr, nullptr, 0, v, DMODEL, nullptr, row0, col0, sm);
}

// ---------------- scalenorm: warp per row (stores tf32-rounded) ----------------
__global__ __launch_bounds__(256)
void scalenorm_kernel(const float* __restrict__ X, float* __restrict__ Y,
                      const float* __restrict__ gptr)
{
    int m = blockIdx.x*8 + (threadIdx.x >> 5);
    int lane = threadIdx.x & 31;
    const float4* x4 = (const float4*)(X + (long)m*DMODEL);
    float4 v[4];
    float ss = 0.f;
    #pragma unroll
    for (int i=0;i<4;i++){
        v[i] = x4[lane + 32*i];
        ss += v[i].x*v[i].x + v[i].y*v[i].y + v[i].z*v[i].z + v[i].w*v[i].w;
    }
    #pragma unroll
    for (int off=16; off; off>>=1) ss += __shfl_xor_sync(0xffffffffu, ss, off);
    float n = sqrtf(ss) * 0.04419417382415922f;
    float f = gptr[0] / fmaxf(n, 1e-5f);
    float4* y4 = (float4*)(Y + (long)m*DMODEL);
    #pragma unroll
    for (int i=0;i<4;i++){
        float4 o;
        o.x = tf32r(v[i].x*f); o.y = tf32r(v[i].y*f);
        o.z = tf32r(v[i].z*f); o.w = tf32r(v[i].w*f);
        y4[lane + 32*i] = o;
    }
}

// ---------------- final layernorm: warp per row (in place; stores tf32-rounded) ----------------
__global__ __launch_bounds__(256)
void layernorm_kernel(float* __restrict__ X,
                      const float* __restrict__ gam, const float* __restrict__ bet)
{
    int m = blockIdx.x*8 + (threadIdx.x >> 5);
    int lane = threadIdx.x & 31;
    float4* x4 = (float4*)(X + (long)m*DMODEL);
    const float4* g4 = (const float4*)gam;
    const float4* b4 = (const float4*)bet;
    float4 v[4];
    float s1 = 0.f, s2 = 0.f;
    #pragma unroll
    for (int i=0;i<4;i++){
        v[i] = x4[lane + 32*i];
        s1 += v[i].x + v[i].y + v[i].z + v[i].w;
        s2 += v[i].x*v[i].x + v[i].y*v[i].y + v[i].z*v[i].z + v[i].w*v[i].w;
    }
    #pragma unroll
    for (int off=16; off; off>>=1) {
        s1 += __shfl_xor_sync(0xffffffffu, s1, off);
        s2 += __shfl_xor_sync(0xffffffffu, s2, off);
    }
    float mu = s1 * (1.f/512.f);
    float var = s2 * (1.f/512.f) - mu*mu;
    float rs = rsqrtf(var + 1e-5f);
    #pragma unroll
    for (int i=0;i<4;i++){
        float4 gg = g4[lane + 32*i];
        float4 bb = b4[lane + 32*i];
        float4 o;
        o.x = tf32r((v[i].x - mu)*rs*gg.x + bb.x);
        o.y = tf32r((v[i].y - mu)*rs*gg.y + bb.y);
        o.z = tf32r((v[i].z - mu)*rs*gg.z + bb.z);
        o.w = tf32r((v[i].w - mu)*rs*gg.w + bb.w);
        x4[lane + 32*i] = o;
    }
}

// ---------------- flash attention (float4 + XOR swizzle; stores rounded O) ----------------
#define FLASH_SMEM ((3*4096 + 1024)*4)
__global__ __launch_bounds__(256)
void flash_attn_kernel(const float* __restrict__ Q, const float* __restrict__ Kg,
                       const float* __restrict__ Vg, float* __restrict__ O)
{
    extern __shared__ float fsm[];
    float* Qs = fsm;
    float* Ks = fsm + 4096;
    float* Vs = fsm + 8192;
    float* bs = fsm + 12288;

    const int tid  = threadIdx.x;
    const int qb   = blockIdx.x;
    const int bh   = blockIdx.y;
    const int b    = bh >> 3, head = bh & 7;
    const int q0   = qb * 64;
    const long base = ((long)b * SEQ) * DMODEL + head * DHEAD;

    const int ty = tid >> 4, tx = tid & 15;
    const int r0 = ty * 4;
    const int c0 = tx * 4;

    for (int i = tid; i < SEQ; i += 256) bs[i] = g_bias[head*SEQ + i];

    #pragma unroll
    for (int i = 0; i < 4; i++) {
        int idx = tid + i*256;
        int rr = idx >> 4, ss = idx & 15;
        float4 v = *(const float4*)(Q + base + (long)(q0+rr)*DMODEL + ss*4);
        *(float4*)&Qs[rr*64 + ((ss ^ (rr>>2)) << 2)] = v;
    }

    float m_run[4], l_run[4], o[4][4];
    #pragma unroll
    for (int i=0;i<4;i++){ m_run[i]=-3.0e38f; l_run[i]=0.f;
        #pragma unroll
        for (int j=0;j<4;j++) o[i][j]=0.f; }

    for (int kt = 0; kt <= qb; kt++) {
        int k0 = kt * 64;
        __syncthreads();
        #pragma unroll
        for (int i = 0; i < 4; i++) {
            int idx = tid + i*256;
            int rr = idx >> 4, ss = idx & 15;
            int sw = ((ss ^ (rr>>2)) << 2);
            float4 kv = *(const float4*)(Kg + base + (long)(k0+rr)*DMODEL + ss*4);
            *(float4*)&Ks[rr*64 + sw] = kv;
            float4 vv = *(const float4*)(Vg + base + (long)(k0+rr)*DMODEL + ss*4);
            *(float4*)&Vs[rr*64 + sw] = vv;
        }
        __syncthreads();

        float s[4][4];
        #pragma unroll
        for (int i=0;i<4;i++)
            #pragma unroll
            for (int j=0;j<4;j++) s[i][j]=0.f;

        #pragma unroll
        for (int kk4 = 0; kk4 < 16; kk4++) {
            float4 q[4], k[4];
            #pragma unroll
            for (int i=0;i<4;i++) q[i] = *(const float4*)&Qs[(r0+i)*64 + ((kk4 ^ ty) << 2)];
            #pragma unroll
            for (int j=0;j<4;j++) k[j] = *(const float4*)&Ks[(c0+j)*64 + ((kk4 ^ tx) << 2)];
            #pragma unroll
            for (int i=0;i<4;i++)
                #pragma unroll
                for (int j=0;j<4;j++) {
                    s[i][j] = fmaf(q[i].x, k[j].x, s[i][j]);
                    s[i][j] = fmaf(q[i].y, k[j].y, s[i][j]);
                    s[i][j] = fmaf(q[i].z, k[j].z, s[i][j]);
                    s[i][j] = fmaf(q[i].w, k[j].w, s[i][j]);
                }
        }

        #pragma unroll
        for (int i=0;i<4;i++) {
            int qi = q0 + r0 + i;
            #pragma unroll
            for (int j=0;j<4;j++) {
                int kj = k0 + c0 + j;
                if (kj > qi) s[i][j] = -3.0e38f;
                else         s[i][j] = s[i][j]*0.125f + bs[qi - kj];
            }
        }
        #pragma unroll
        for (int i=0;i<4;i++) {
            float mx = fmaxf(fmaxf(s[i][0],s[i][1]),fmaxf(s[i][2],s[i][3]));
            mx = fmaxf(mx, __shfl_xor_sync(0xffffffffu, mx, 8));
            mx = fmaxf(mx, __shfl_xor_sync(0xffffffffu, mx, 4));
            mx = fmaxf(mx, __shfl_xor_sync(0xffffffffu, mx, 2));
            mx = fmaxf(mx, __shfl_xor_sync(0xffffffffu, mx, 1));
            float m_new = fmaxf(m_run[i], mx);
            float alpha = __expf(m_run[i] - m_new);
            float ls = 0.f;
            #pragma unroll
            for (int j=0;j<4;j++) { s[i][j] = __expf(s[i][j] - m_new); ls += s[i][j]; }
            ls += __shfl_xor_sync(0xffffffffu, ls, 8);
            ls += __shfl_xor_sync(0xffffffffu, ls, 4);
            ls += __shfl_xor_sync(0xffffffffu, ls, 2);
            ls += __shfl_xor_sync(0xffffffffu, ls, 1);
            l_run[i] = l_run[i]*alpha + ls;
            m_run[i] = m_new;
            #pragma unroll
            for (int j=0;j<4;j++) o[i][j] *= alpha;
        }
        __syncthreads();
        #pragma unroll
        for (int i=0;i<4;i++)
            *(float4*)&Ks[(r0+i)*64 + ((tx ^ ty) << 2)] =
                make_float4(s[i][0], s[i][1], s[i][2], s[i][3]);
        __syncthreads();

        #pragma unroll
        for (int jj4 = 0; jj4 < 16; jj4++) {
            float4 p[4], v[4];
            #pragma unroll
            for (int i=0;i<4;i++) p[i] = *(const float4*)&Ks[(r0+i)*64 + ((jj4 ^ ty) << 2)];
            #pragma unroll
            for (int u=0;u<4;u++) v[u] = *(const float4*)&Vs[(4*jj4+u)*64 + ((tx ^ jj4) << 2)];
            #pragma unroll
            for (int i=0;i<4;i++) {
                float pc[4] = {p[i].x, p[i].y, p[i].z, p[i].w};
                #pragma unroll
                for (int u=0;u<4;u++) {
                    o[i][0] = fmaf(pc[u], v[u].x, o[i][0]);
                    o[i][1] = fmaf(pc[u], v[u].y, o[i][1]);
                    o[i][2] = fmaf(pc[u], v[u].z, o[i][2]);
                    o[i][3] = fmaf(pc[u], v[u].w, o[i][3]);
                }
            }
        }
    }
    #pragma unroll
    for (int i=0;i<4;i++){
        float inv_l = 1.f / l_run[i];
        #pragma unroll
        for (int j=0;j<4;j++)
            O[base + (long)(q0 + r0 + i)*DMODEL + c0 + j] = tf32r(o[i][j]*inv_l);
    }
}

// ---------------- launch ----------------
static inline dim3 gemm_grid(int N) { return dim3((N + 127)/128, MTOT/128); }

extern "C" void kernel_launch(void* const* d_in, const int* in_sizes, int n_in,
                              void* d_out, int out_size)
{
    const float* saml       = (const float*)d_in[0];
    const float* emb_table  = (const float*)d_in[1];
    const float* proj_in_w  = (const float*)d_in[2];
    const float* proj_in_b  = (const float*)d_in[3];
    const float* ga         = (const float*)d_in[4];
    const float* gf         = (const float*)d_in[5];
    const float* Wq         = (const float*)d_in[6];
    const float* Wk         = (const float*)d_in[7];
    const float* Wv         = (const float*)d_in[8];
    const float* Wo         = (const float*)d_in[9];
    const float* bo         = (const float*)d_in[10];
    const float* relpos     = (const float*)d_in[11];
    const float* W1         = (const float*)d_in[12];
    const float* b1         = (const float*)d_in[13];
    const float* W2         = (const float*)d_in[14];
    const float* b2         = (const float*)d_in[15];
    const float* ln_g       = (const float*)d_in[16];
    const float* ln_b       = (const float*)d_in[17];
    const float* proj_out_w = (const float*)d_in[18];
    const float* proj_out_b = (const float*)d_in[19];
    const float* cls_w      = (const float*)d_in[20];
    const float* cls_b      = (const float*)d_in[21];
    float* outp = (float*)d_out;

    float *px, *ph, *phn, *pq, *pk, *pv, *po, *pff, *pout, *pwt;
    cudaGetSymbolAddress((void**)&px,  g_x);
    cudaGetSymbolAddress((void**)&ph,  g_h);
    cudaGetSymbolAddress((void**)&phn, g_hn);
    cudaGetSymbolAddress((void**)&pq,  g_q);
    cudaGetSymbolAddress((void**)&pk,  g_k);
    cudaGetSymbolAddress((void**)&pv,  g_v);
    cudaGetSymbolAddress((void**)&po,  g_o);
    cudaGetSymbolAddress((void**)&pff, g_ff);
    cudaGetSymbolAddress((void**)&pout,g_out2);
    cudaGetSymbolAddress((void**)&pwt, g_wt);

    cudaFuncSetAttribute(tgemm_kernel<1,false,0,0>, cudaFuncAttributeMaxDynamicSharedMemorySize, GEMM_SMEM);
    cudaFuncSetAttribute(tgemm_kernel<2,false,0,0>, cudaFuncAttributeMaxDynamicSharedMemorySize, GEMM_SMEM);
    cudaFuncSetAttribute(tgemm_kernel<3,false,1,0>, cudaFuncAttributeMaxDynamicSharedMemorySize, GEMM_SMEM);
    cudaFuncSetAttribute(tgemm_kernel<1,false,2,1>, cudaFuncAttributeMaxDynamicSharedMemorySize, GEMM_SMEM);
    cudaFuncSetAttribute(tgemm_kernel<1,true ,0,0>, cudaFuncAttributeMaxDynamicSharedMemorySize, GEMM_SMEM);
    cudaFuncSetAttribute(qkv_kernel,                cudaFuncAttributeMaxDynamicSharedMemorySize, GEMM_SMEM);
    cudaFuncSetAttribute(flash_attn_kernel,         cudaFuncAttributeMaxDynamicSharedMemorySize, FLASH_SMEM);

    // transpose + tf32-round all weights: src[K][N] -> dst[N][K]
    {
        auto tr = [](const float* s, float* d, int K, int N, int z) {
            transpose_round_kernel<<<dim3((N+31)/32, (K+31)/32, z), 256>>>(s, d, K, N);
        };
        tr(proj_in_w,  pwt + OFF_PIN,  DIN,    DMODEL, 1);
        tr(Wq,         pwt + OFF_WQ,   DMODEL, DMODEL, 6);
        tr(Wk,         pwt + OFF_WK,   DMODEL, DMODEL, 6);
        tr(Wv,         pwt + OFF_WV,   DMODEL, DMODEL, 6);
        tr(Wo,         pwt + OFF_WO,   DMODEL, DMODEL, 6);
        tr(W1,         pwt + OFF_W1,   DMODEL, DFF,    6);
        tr(W2,         pwt + OFF_W2,   DFF,    DMODEL, 6);
        tr(proj_out_w, pwt + OFF_POUT, DMODEL, DIN,    1);
        tr(cls_w,      pwt + OFF_CLS,  DMODEL, NCLS,   1);
    }

    bias_table_kernel<<<4, 256>>>(relpos);
    embed_kernel<<<MTOT, 256>>>(saml, emb_table);

    tgemm_kernel<1,false,0,0><<<gemm_grid(DMODEL), 256, GEMM_SMEM>>>(MTOT, DMODEL, DIN,
        px, DIN, pwt + OFF_PIN, proj_in_b, nullptr, 0, ph, DMODEL, nullptr);

    for (int l = 0; l < 6; l++) {
        const float* wq = pwt + OFF_WQ + (long)l*SZ_W;
        const float* wk = pwt + OFF_WK + (long)l*SZ_W;
        const float* wv = pwt + OFF_WV + (long)l*SZ_W;
        const float* wo = pwt + OFF_WO + (long)l*SZ_W;
        const float* w1 = pwt + OFF_W1 + (long)l*SZ_W1;
        const float* w2 = pwt + OFF_W2 + (long)l*SZ_W1;

        scalenorm_kernel<<<MTOT/8, 256>>>(ph, phn, ga + l);
        qkv_kernel<<<dim3(12, MTOT/128), 256, GEMM_SMEM>>>(phn, wq, wk, wv, pq, pk, pv);
        flash_attn_kernel<<<dim3(SEQ/64, BATCH*NHEADS), 256, FLASH_SMEM>>>(pq, pk, pv, po);
        tgemm_kernel<2,false,0,0><<<gemm_grid(DMODEL), 256, GEMM_SMEM>>>(MTOT, DMODEL, DMODEL,
            po, DMODEL, wo, bo + (long)l*DMODEL, ph, DMODEL, ph, DMODEL, nullptr);
        scalenorm_kernel<<<MTOT/8, 256>>>(ph, phn, gf + l);
        tgemm_kernel<3,false,1,0><<<gemm_grid(DFF), 256, GEMM_SMEM>>>(MTOT, DFF, DMODEL,
            phn, DMODEL, w1, b1 + (long)l*DFF, nullptr, 0, pff, DFF, nullptr);
        tgemm_kernel<2,false,0,0><<<gemm_grid(DMODEL), 256, GEMM_SMEM>>>(MTOT, DMODEL, DFF,
            pff, DFF, w2, b2 + (long)l*DMODEL, ph, DMODEL, ph, DMODEL, nullptr);
    }

    layernorm_kernel<<<MTOT/8, 256>>>(ph, ln_g, ln_b);
    // out = h @ proj_out_w + b; cols<512 -> g_out2 (rounded), cols>=512 -> d_out tail (exact)
    tgemm_kernel<1,false,2,1><<<gemm_grid(DIN), 256, GEMM_SMEM>>>(MTOT, DIN, DMODEL,
        ph, DMODEL, pwt + OFF_POUT, proj_out_b, nullptr, 0, pout, DIN, outp);
    // classifier logits, stored transposed into d_out
    tgemm_kernel<1,true,0,0><<<gemm_grid(NCLS), 256, GEMM_SMEM>>>(MTOT, NCLS, DMODEL,
        pout, DIN, pwt + OFF_CLS, cls_b, nullptr, 0, outp, 0, nullptr);
}

// round 15
// speedup vs baseline: 1.0946x; 1.0946x over previous
#include <cuda_runtime.h>
#include <math.h>
#include <stdint.h>

#define SEQ 1024
#define BATCH 8
#define MTOT (BATCH*SEQ)   // 8192
#define NHEADS 8
#define DHEAD 64
#define DMODEL 512
#define DIN 524
#define DFF 2048
#define NCLS 1024
#define OUTROW 1036

// ---------------- scratch (device globals; no allocation allowed) ----------------
__device__ float g_x [MTOT*DIN];
__device__ float g_h [MTOT*DMODEL];
__device__ float g_hn[MTOT*DMODEL];
__device__ float g_q [MTOT*DMODEL];
__device__ float g_k [MTOT*DMODEL];
__device__ float g_v [MTOT*DMODEL];
__device__ float g_o [MTOT*DMODEL];
__device__ float g_ff[MTOT*DFF];
__device__ float g_out2[MTOT*DIN];
__device__ float g_bias[NHEADS*SEQ];

// pre-rounded (tf32) weight storage
#define SZ_PIN  (DIN*DMODEL)
#define SZ_W    (DMODEL*DMODEL)
#define SZ_W1   (DMODEL*DFF)
#define SZ_POUT (DMODEL*DIN)
#define SZ_CLS  (DMODEL*NCLS)
#define OFF_PIN  0
#define OFF_WQ   (OFF_PIN + SZ_PIN)
#define OFF_WK   (OFF_WQ + 6*SZ_W)
#define OFF_WV   (OFF_WK + 6*SZ_W)
#define OFF_WO   (OFF_WV + 6*SZ_W)
#define OFF_W1   (OFF_WO + 6*SZ_W)
#define OFF_W2   (OFF_W1 + 6*SZ_W1)
#define OFF_POUT (OFF_W2 + 6*SZ_W1)
#define OFF_CLS  (OFF_POUT + SZ_POUT)
#define WT_TOTAL (OFF_CLS + SZ_CLS)
__device__ float g_wt[WT_TOTAL];

// ---------------- tf32 helpers ----------------
__device__ __forceinline__ uint32_t f2tf32(float f) {
    uint32_t r;
    asm("cvt.rna.tf32.f32 %0, %1;" : "=r"(r) : "f"(f));
    return r;
}
__device__ __forceinline__ float tf32r(float f) {
    return __uint_as_float(f2tf32(f));
}
__device__ __forceinline__ void mma_tf32(float* c,
    uint32_t a0, uint32_t a1, uint32_t a2, uint32_t a3,
    uint32_t b0, uint32_t b1)
{
    asm volatile(
        "mma.sync.aligned.m16n8k8.row.col.f32.tf32.tf32.f32 "
        "{%0,%1,%2,%3}, {%4,%5,%6,%7}, {%8,%9}, {%0,%1,%2,%3};"
        : "+f"(c[0]), "+f"(c[1]), "+f"(c[2]), "+f"(c[3])
        : "r"(a0), "r"(a1), "r"(a2), "r"(a3), "r"(b0), "r"(b1));
}
__device__ __forceinline__ void ldmatrix_x4(uint32_t& r0, uint32_t& r1,
                                            uint32_t& r2, uint32_t& r3,
                                            uint32_t saddr)
{
    asm volatile("ldmatrix.sync.aligned.m8n8.x4.shared.b16 {%0,%1,%2,%3}, [%4];"
                 : "=r"(r0), "=r"(r1), "=r"(r2), "=r"(r3) : "r"(saddr));
}
__device__ __forceinline__ void cp_async16(float* dst, const float* src, bool pred) {
    uint32_t d = (uint32_t)__cvta_generic_to_shared(dst);
    int bytes = pred ? 16 : 0;
    asm volatile("cp.async.cg.shared.global [%0], [%1], 16, %2;\n"
                 :: "r"(d), "l"(src), "r"(bytes));
}
__device__ __forceinline__ void cp_commit() {
    asm volatile("cp.async.commit_group;\n" ::);
}
template<int N>
__device__ __forceinline__ void cp_wait() {
    asm volatile("cp.async.wait_group %0;\n" :: "n"(N));
}

// ---------------- merged weight tf32 pre-round (single launch) ----------------
struct CvtSrcs { const float* s[9]; };
__global__ __launch_bounds__(256)
void cvt_all_kernel(CvtSrcs a, float* __restrict__ dst)
{
    long i4 = (long)blockIdx.x*256 + threadIdx.x;
    long e = i4*4;
    if (e >= WT_TOTAL) return;
    const float* src; long base;
    if      (e < OFF_WQ)   { src = a.s[0]; base = OFF_PIN;  }
    else if (e < OFF_WK)   { src = a.s[1]; base = OFF_WQ;   }
    else if (e < OFF_WV)   { src = a.s[2]; base = OFF_WK;   }
    else if (e < OFF_WO)   { src = a.s[3]; base = OFF_WV;   }
    else if (e < OFF_W1)   { src = a.s[4]; base = OFF_WO;   }
    else if (e < OFF_W2)   { src = a.s[5]; base = OFF_W1;   }
    else if (e < OFF_POUT) { src = a.s[6]; base = OFF_W2;   }
    else if (e < OFF_CLS)  { src = a.s[7]; base = OFF_POUT; }
    else                   { src = a.s[8]; base = OFF_CLS;  }
    float4 v = ((const float4*)src)[(e - base) >> 2];
    v.x = tf32r(v.x); v.y = tf32r(v.y); v.z = tf32r(v.z); v.w = tf32r(v.w);
    ((float4*)dst)[i4] = v;
}

// ---------------- relpos bias table ----------------
__global__ void bias_table_kernel(const float* __restrict__ relpos)
{
    int n = blockIdx.x * blockDim.x + threadIdx.x;
    if (n >= SEQ) return;
    int bucket;
    if (n < 4) {
        bucket = n;
    } else {
        int vl = 4 + (int)(logf((float)n * 0.25f) * (4.0f / logf(8.0f)));
        bucket = vl < 7 ? vl : 7;
    }
    for (int h = 0; h < NHEADS; h++)
        g_bias[h*SEQ + n] = relpos[bucket*NHEADS + h] * 8.0f;  // * DIM_HEAD**0.5
}

// ---------------- embedding gather + concat (stores tf32-rounded) ----------------
__global__ __launch_bounds__(256)
void embed_kernel(const float* __restrict__ saml, const float* __restrict__ emb)
{
    int m = blockIdx.x;
    int b = m >> 10, s = m & 1023;
    const float* row = saml + ((long)b*1025 + s)*13;
    int id = (int)row[0];
    float* x = g_x + (long)m*DIN;
    const float* erow = emb + (long)id*512;
    for (int c = threadIdx.x; c < DIN; c += 256)
        x[c] = tf32r((c < 512) ? erow[c] : row[c - 511]);
}

// ---------------- TF32 tensor-core GEMM body (2-stage cp.async + ldmatrix A) ----------------
// Epilogue staged through smem for coalesced stores.
// TAILM: cols >= 512 go directly to Tout (final output tail), unrounded.
#define LDA_S 36
#define LDB_S 136
#define ASTG (128*LDA_S)
#define BSTG (32*LDB_S)
#define GEMM_SMEM ((2*(ASTG+BSTG))*4)
#define STG_LD 132

template<int MODE, bool TSTORE, bool ROT, int RND, int TAILM>
__device__ __forceinline__
void gemm_body(int M, int N, int K,
               const float* __restrict__ A, int lda,
               const float* __restrict__ B, int ldb,
               const float* __restrict__ bias,
               const float* __restrict__ Res, int ldr,
               float* __restrict__ C, int ldc,
               float* __restrict__ Tout,
               int row0, int col0, float* sm)
{
    float* As = sm;
    float* Bs = sm + 2*ASTG;

    const int tid  = threadIdx.x;
    const int wid  = tid >> 5;
    const int lane = tid & 31;
    const int g    = lane >> 2;
    const int tg   = lane & 3;
    const int wm   = wid >> 2;
    const int wn   = wid & 3;

    const int l8 = lane & 7;
    const int lf8 = ((lane >> 3) & 1) * 8;
    const int lk4 = (lane >> 4) * 4;
    const uint32_t a_sbase = (uint32_t)__cvta_generic_to_shared(As)
        + (uint32_t)(((wm*64 + l8 + lf8)*LDA_S + lk4) * 4);

    float acc[4][4][4];
    #pragma unroll
    for (int mi=0;mi<4;mi++)
        #pragma unroll
        for (int ni=0;ni<4;ni++)
            #pragma unroll
            for (int r=0;r<4;r++) acc[mi][ni][r]=0.f;

    const int nt = (K + 31) / 32;

#define LOAD_TILE(STG, KT)                                                        \
    {                                                                             \
        _Pragma("unroll")                                                         \
        for (int i = 0; i < 4; i++) {                                             \
            int idx = tid + i*256;                                                \
            int r  = idx >> 3;                                                    \
            int c4 = (idx & 7) * 4;                                               \
            int k4 = (KT) + c4;                                                   \
            bool p = (k4 < K);                                                    \
            const float* src = A + (long)(row0 + r)*lda + (p ? k4 : 0);           \
            cp_async16(As + (STG)*ASTG + r*LDA_S + c4, src, p);                   \
        }                                                                         \
        _Pragma("unroll")                                                         \
        for (int i = 0; i < 4; i++) {                                             \
            int idx = tid + i*256;                                                \
            int kk = idx >> 5;                                                    \
            int n4 = (idx & 31) * 4;                                              \
            int k  = (KT) + kk;                                                   \
            int c  = col0 + n4;                                                   \
            bool p = (k < K) && (c < N);                                          \
            const float* src = B + (long)(p ? k : 0)*ldb + (p ? c : 0);           \
            cp_async16(Bs + (STG)*BSTG + kk*LDB_S + n4, src, p);                  \
        }                                                                         \
        cp_commit();                                                              \
    }

    LOAD_TILE(0, 0)

    for (int t = 0; t < nt; t++) {
        if (t + 1 < nt) {
            LOAD_TILE((t+1)&1, (t+1)*32)
            cp_wait<1>();
        } else {
            cp_wait<0>();
        }
        __syncthreads();

        const uint32_t a_st = a_sbase + (uint32_t)((t&1)*ASTG*4);
        const uint32_t* Bc = (const uint32_t*)(Bs + (t&1)*BSTG);
        #pragma unroll
        for (int ks = 0; ks < 4; ks++) {
            const int k8 = ks*8;
            uint32_t a[4][4], b[4][2];
            #pragma unroll
            for (int mi=0;mi<4;mi++)
                ldmatrix_x4(a[mi][0], a[mi][1], a[mi][2], a[mi][3],
                            a_st + (uint32_t)((mi*16*LDA_S + k8) * 4));
            #pragma unroll
            for (int ni=0;ni<4;ni++) {
                int nc = wn*32 + ni*8 + g;
                b[ni][0] = Bc[(k8+tg  )*LDB_S + nc];
                b[ni][1] = Bc[(k8+tg+4)*LDB_S + nc];
            }
            #pragma unroll
            for (int mi=0;mi<4;mi++)
                #pragma unroll
                for (int ni=0;ni<4;ni++)
                    mma_tf32(acc[mi][ni], a[mi][0],a[mi][1],a[mi][2],a[mi][3],
                             b[ni][0], b[ni][1]);
        }
        __syncthreads();
    }
#undef LOAD_TILE

    // ---- rotary on accumulators (Q/K projections only) ----
    if (ROT && ((wn & 1) == 0)) {
        #pragma unroll
        for (int mi=0;mi<4;mi++) {
            #pragma unroll
            for (int r=0;r<4;r++) {
                int row = row0 + wm*64 + mi*16 + g + ((r>=2)?8:0);
                int s = row & 1023;
                #pragma unroll
                for (int ni=0;ni<2;ni++) {
                    int d = ni*8 + tg*2 + (r&1);
                    float inv = expf(-(float)(2*d) * (9.210340371976184f/32.f));
                    float ang = (float)s * inv;
                    float sn, c;
                    sincosf(ang, &sn, &c);
                    float a = acc[mi][ni][r];
                    float bb = acc[mi][ni+2][r];
                    acc[mi][ni  ][r] = a*c - bb*sn;
                    acc[mi][ni+2][r] = bb*c + a*sn;
                }
            }
        }
    }

    // ---- staged epilogue: two passes of 64 rows through smem ----
    float* stage = sm;
    #pragma unroll
    for (int p = 0; p < 2; p++) {
        __syncthreads();
        if (wm == p) {
            #pragma unroll
            for (int mi=0;mi<4;mi++)
                #pragma unroll
                for (int ni=0;ni<4;ni++)
                    #pragma unroll
                    for (int r=0;r<4;r++) {
                        int lr = mi*16 + g + ((r>=2)?8:0);
                        int lc = wn*32 + ni*8 + tg*2 + (r&1);
                        stage[lr*STG_LD + lc] = acc[mi][ni][r];
                    }
        }
        __syncthreads();
        if (TSTORE) {
            #pragma unroll
            for (int i = 0; i < 8; i++) {
                int idx = tid + i*256;
                int col = idx & 127;
                int r4  = (idx >> 7) * 4;
                int gcol = col0 + col;
                float o4[4];
                #pragma unroll
                for (int j = 0; j < 4; j++)
                    o4[j] = stage[(r4+j)*STG_LD + col] + bias[gcol];
                int b_ = row0 >> 10;
                int s_ = (row0 & 1023) + p*64 + r4;
                *(float4*)&C[(long)b_*(NCLS*OUTROW) + (long)gcol*OUTROW + s_] = *(float4*)o4;
            }
        } else {
            #pragma unroll
            for (int i = 0; i < 8; i++) {
                int idx = tid + i*256;
                int r  = idx >> 5;
                int c4 = (idx & 31) * 4;
                int row = row0 + p*64 + r;
                int col = col0 + c4;
                float4 v = *(float4*)&stage[r*STG_LD + c4];
                float vv[4] = {v.x, v.y, v.z, v.w};
                bool fastvec = (col + 3 < N) && (!TAILM || (col + 3 < 512));
                if (fastvec) {
                    if (MODE >= 1) {
                        float4 bb = *(const float4*)&bias[col];
                        vv[0]+=bb.x; vv[1]+=bb.y; vv[2]+=bb.z; vv[3]+=bb.w;
                    }
                    if (MODE == 2) {
                        float4 rr = *(const float4*)&Res[(long)row*ldr + col];
                        vv[0]+=rr.x; vv[1]+=rr.y; vv[2]+=rr.z; vv[3]+=rr.w;
                    }
                    #pragma unroll
                    for (int j = 0; j < 4; j++) {
                        float x = vv[j];
                        if (MODE == 3) x = 0.5f*x*(1.f + erff(x*0.7071067811865476f));
                        if (RND == 1) x = tf32r(x);
                        if (RND == 2 && col + j < 512) x = tf32r(x);
                        vv[j] = x;
                    }
                    *(float4*)&C[(long)row*ldc + col] = make_float4(vv[0],vv[1],vv[2],vv[3]);
                } else {
                    #pragma unroll
                    for (int j = 0; j < 4; j++) {
                        int cc = col + j;
                        if (cc < N) {
                            float x = vv[j];
                            if (MODE >= 1) x += bias[cc];
                            if (MODE == 2) x += Res[(long)row*ldr + cc];
                            if (MODE == 3) x = 0.5f*x*(1.f + erff(x*0.7071067811865476f));
                            if (TAILM && cc >= 512) {
                                int b_ = row >> 10, s_ = row & 1023;
                                Tout[(long)b_*(NCLS*OUTROW) + (long)s_*OUTROW + NCLS + (cc - 512)] = x;
                            } else {
                                if (RND == 1) x = tf32r(x);
                                if (RND == 2 && cc < 512) x = tf32r(x);
                                C[(long)row*ldc + cc] = x;
                            }
                        }
                    }
                }
            }
        }
    }
}

template<int MODE, bool TSTORE, int RND, int TAILM>
__global__ __launch_bounds__(256)
void tgemm_kernel(int M, int N, int K,
                  const float* __restrict__ A, int lda,
                  const float* __restrict__ B, int ldb,
                  const float* __restrict__ bias,
                  const float* __restrict__ Res, int ldr,
                  float* __restrict__ C, int ldc,
                  float* __restrict__ Tout)
{
    extern __shared__ float sm[];
    gemm_body<MODE,TSTORE,false,RND,TAILM>(M, N, K, A, lda, B, ldb, bias, Res, ldr,
                                           C, ldc, Tout,
                                           blockIdx.y*128, blockIdx.x*128, sm);
}

// fused QKV with rotary on Q/K outputs: grid (12, 64)
__global__ __launch_bounds__(256)
void qkv_kernel(const float* __restrict__ A,
                const float* __restrict__ wq, const float* __restrict__ wk,
                const float* __restrict__ wv,
                float* __restrict__ q, float* __restrict__ k, float* __restrict__ v)
{
    extern __shared__ float sm[];
    int sel = blockIdx.x >> 2;
    int row0 = blockIdx.y*128, col0 = (blockIdx.x & 3)*128;
    if (sel == 0)
        gemm_body<0,false,true ,0,0>(MTOT, DMODEL, DMODEL, A, DMODEL, wq, DMODEL,
                                     nullptr, nullptr, 0, q, DMODEL, nullptr, row0, col0, sm);
    else if (sel == 1)
        gemm_body<0,false,true ,0,0>(MTOT, DMODEL, DMODEL, A, DMODEL, wk, DMODEL,
                                     nullptr, nullptr, 0, k, DMODEL, nullptr, row0, col0, sm);
    else
        gemm_body<0,false,false,0,0>(MTOT, DMODEL, DMODEL, A, DMODEL, wv, DMODEL,
                                     nullptr, nullptr, 0, v, DMODEL, nullptr, row0, col0, sm);
}

// ---------------- scalenorm: warp per row (stores tf32-rounded) ----------------
__global__ __launch_bounds__(256)
void scalenorm_kernel(const float* __restrict__ X, float* __restrict__ Y,
                      const float* __restrict__ gptr)
{
    int m = blockIdx.x*8 + (threadIdx.x >> 5);
    int lane = threadIdx.x & 31;
    const float4* x4 = (const float4*)(X + (long)m*DMODEL);
    float4 v[4];
    float ss = 0.f;
    #pragma unroll
    for (int i=0;i<4;i++){
        v[i] = x4[lane + 32*i];
        ss += v[i].x*v[i].x + v[i].y*v[i].y + v[i].z*v[i].z + v[i].w*v[i].w;
    }
    #pragma unroll
    for (int off=16; off; off>>=1) ss += __shfl_xor_sync(0xffffffffu, ss, off);
    float n = sqrtf(ss) * 0.04419417382415922f;
    float f = gptr[0] / fmaxf(n, 1e-5f);
    float4* y4 = (float4*)(Y + (long)m*DMODEL);
    #pragma unroll
    for (int i=0;i<4;i++){
        float4 o;
        o.x = tf32r(v[i].x*f); o.y = tf32r(v[i].y*f);
        o.z = tf32r(v[i].z*f); o.w = tf32r(v[i].w*f);
        y4[lane + 32*i] = o;
    }
}

// ---------------- final layernorm: warp per row (in place; stores tf32-rounded) ----------------
__global__ __launch_bounds__(256)
void layernorm_kernel(float* __restrict__ X,
                      const float* __restrict__ gam, const float* __restrict__ bet)
{
    int m = blockIdx.x*8 + (threadIdx.x >> 5);
    int lane = threadIdx.x & 31;
    float4* x4 = (float4*)(X + (long)m*DMODEL);
    const float4* g4 = (const float4*)gam;
    const float4* b4 = (const float4*)bet;
    float4 v[4];
    float s1 = 0.f, s2 = 0.f;
    #pragma unroll
    for (int i=0;i<4;i++){
        v[i] = x4[lane + 32*i];
        s1 += v[i].x + v[i].y + v[i].z + v[i].w;
        s2 += v[i].x*v[i].x + v[i].y*v[i].y + v[i].z*v[i].z + v[i].w*v[i].w;
    }
    #pragma unroll
    for (int off=16; off; off>>=1) {
        s1 += __shfl_xor_sync(0xffffffffu, s1, off);
        s2 += __shfl_xor_sync(0xffffffffu, s2, off);
    }
    float mu = s1 * (1.f/512.f);
    float var = s2 * (1.f/512.f) - mu*mu;
    float rs = rsqrtf(var + 1e-5f);
    #pragma unroll
    for (int i=0;i<4;i++){
        float4 gg = g4[lane + 32*i];
        float4 bb = b4[lane + 32*i];
        float4 o;
        o.x = tf32r((v[i].x - mu)*rs*gg.x + bb.x);
        o.y = tf32r((v[i].y - mu)*rs*gg.y + bb.y);
        o.z = tf32r((v[i].z - mu)*rs*gg.z + bb.z);
        o.w = tf32r((v[i].w - mu)*rs*gg.w + bb.w);
        x4[lane + 32*i] = o;
    }
}

// ---------------- flash attention (float4 + XOR swizzle; stores rounded O) ----------------
// P staging rows are ty-group-local (same warp), so the post-P barrier is a __syncwarp.
#define FLASH_SMEM ((3*4096 + 1024)*4)
__global__ __launch_bounds__(256)
void flash_attn_kernel(const float* __restrict__ Q, const float* __restrict__ Kg,
                       const float* __restrict__ Vg, float* __restrict__ O)
{
    extern __shared__ float fsm[];
    float* Qs = fsm;
    float* Ks = fsm + 4096;
    float* Vs = fsm + 8192;
    float* bs = fsm + 12288;

    const int tid  = threadIdx.x;
    const int qb   = blockIdx.x;
    const int bh   = blockIdx.y;
    const int b    = bh >> 3, head = bh & 7;
    const int q0   = qb * 64;
    const long base = ((long)b * SEQ) * DMODEL + head * DHEAD;

    const int ty = tid >> 4, tx = tid & 15;
    const int r0 = ty * 4;
    const int c0 = tx * 4;

    for (int i = tid; i < SEQ; i += 256) bs[i] = g_bias[head*SEQ + i];

    #pragma unroll
    for (int i = 0; i < 4; i++) {
        int idx = tid + i*256;
        int rr = idx >> 4, ss = idx & 15;
        float4 v = *(const float4*)(Q + base + (long)(q0+rr)*DMODEL + ss*4);
        *(float4*)&Qs[rr*64 + ((ss ^ (rr>>2)) << 2)] = v;
    }

    float m_run[4], l_run[4], o[4][4];
    #pragma unroll
    for (int i=0;i<4;i++){ m_run[i]=-3.0e38f; l_run[i]=0.f;
        #pragma unroll
        for (int j=0;j<4;j++) o[i][j]=0.f; }

    for (int kt = 0; kt <= qb; kt++) {
        int k0 = kt * 64;
        __syncthreads();
        #pragma unroll
        for (int i = 0; i < 4; i++) {
            int idx = tid + i*256;
            int rr = idx >> 4, ss = idx & 15;
            int sw = ((ss ^ (rr>>2)) << 2);
            float4 kv = *(const float4*)(Kg + base + (long)(k0+rr)*DMODEL + ss*4);
            *(float4*)&Ks[rr*64 + sw] = kv;
            float4 vv = *(const float4*)(Vg + base + (long)(k0+rr)*DMODEL + ss*4);
            *(float4*)&Vs[rr*64 + sw] = vv;
        }
        __syncthreads();

        float s[4][4];
        #pragma unroll
        for (int i=0;i<4;i++)
            #pragma unroll
            for (int j=0;j<4;j++) s[i][j]=0.f;

        #pragma unroll
        for (int kk4 = 0; kk4 < 16; kk4++) {
            float4 q[4], k[4];
            #pragma unroll
            for (int i=0;i<4;i++) q[i] = *(const float4*)&Qs[(r0+i)*64 + ((kk4 ^ ty) << 2)];
            #pragma unroll
            for (int j=0;j<4;j++) k[j] = *(const float4*)&Ks[(c0+j)*64 + ((kk4 ^ tx) << 2)];
            #pragma unroll
            for (int i=0;i<4;i++)
                #pragma unroll
                for (int j=0;j<4;j++) {
                    s[i][j] = fmaf(q[i].x, k[j].x, s[i][j]);
                    s[i][j] = fmaf(q[i].y, k[j].y, s[i][j]);
                    s[i][j] = fmaf(q[i].z, k[j].z, s[i][j]);
                    s[i][j] = fmaf(q[i].w, k[j].w, s[i][j]);
                }
        }

        #pragma unroll
        for (int i=0;i<4;i++) {
            int qi = q0 + r0 + i;
            #pragma unroll
            for (int j=0;j<4;j++) {
                int kj = k0 + c0 + j;
                if (kj > qi) s[i][j] = -3.0e38f;
                else         s[i][j] = s[i][j]*0.125f + bs[qi - kj];
            }
        }
        #pragma unroll
        for (int i=0;i<4;i++) {
            float mx = fmaxf(fmaxf(s[i][0],s[i][1]),fmaxf(s[i][2],s[i][3]));
            mx = fmaxf(mx, __shfl_xor_sync(0xffffffffu, mx, 8));
            mx = fmaxf(mx, __shfl_xor_sync(0xffffffffu, mx, 4));
            mx = fmaxf(mx, __shfl_xor_sync(0xffffffffu, mx, 2));
            mx = fmaxf(mx, __shfl_xor_sync(0xffffffffu, mx, 1));
            float m_new = fmaxf(m_run[i], mx);
            float alpha = __expf(m_run[i] - m_new);
            float ls = 0.f;
            #pragma unroll
            for (int j=0;j<4;j++) { s[i][j] = __expf(s[i][j] - m_new); ls += s[i][j]; }
            ls += __shfl_xor_sync(0xffffffffu, ls, 8);
            ls += __shfl_xor_sync(0xffffffffu, ls, 4);
            ls += __shfl_xor_sync(0xffffffffu, ls, 2);
            ls += __shfl_xor_sync(0xffffffffu, ls, 1);
            l_run[i] = l_run[i]*alpha + ls;
            m_run[i] = m_new;
            #pragma unroll
            for (int j=0;j<4;j++) o[i][j] *= alpha;
        }
        __syncthreads();   // all warps done reading K from Ks before P overwrites it
        #pragma unroll
        for (int i=0;i<4;i++)
            *(float4*)&Ks[(r0+i)*64 + ((tx ^ ty) << 2)] =
                make_float4(s[i][0], s[i][1], s[i][2], s[i][3]);
        __syncwarp();      // P rows r0..r0+3 are produced & consumed by this warp only

        #pragma unroll
        for (int jj4 = 0; jj4 < 16; jj4++) {
            float4 p[4], v[4];
            #pragma unroll
            for (int i=0;i<4;i++) p[i] = *(const float4*)&Ks[(r0+i)*64 + ((jj4 ^ ty) << 2)];
            #pragma unroll
            for (int u=0;u<4;u++) v[u] = *(const float4*)&Vs[(4*jj4+u)*64 + ((tx ^ jj4) << 2)];
            #pragma unroll
            for (int i=0;i<4;i++) {
                float pc[4] = {p[i].x, p[i].y, p[i].z, p[i].w};
                #pragma unroll
                for (int u=0;u<4;u++) {
                    o[i][0] = fmaf(pc[u], v[u].x, o[i][0]);
                    o[i][1] = fmaf(pc[u], v[u].y, o[i][1]);
                    o[i][2] = fmaf(pc[u], v[u].z, o[i][2]);
                    o[i][3] = fmaf(pc[u], v[u].w, o[i][3]);
                }
            }
        }
    }
    #pragma unroll
    for (int i=0;i<4;i++){
        float inv_l = 1.f / l_run[i];
        #pragma unroll
        for (int j=0;j<4;j++)
            O[base + (long)(q0 + r0 + i)*DMODEL + c0 + j] = tf32r(o[i][j]*inv_l);
    }
}

// ---------------- launch ----------------
static inline dim3 gemm_grid(int N) { return dim3((N + 127)/128, MTOT/128); }

extern "C" void kernel_launch(void* const* d_in, const int* in_sizes, int n_in,
                              void* d_out, int out_size)
{
    const float* saml       = (const float*)d_in[0];
    const float* emb_table  = (const float*)d_in[1];
    const float* proj_in_w  = (const float*)d_in[2];
    const float* proj_in_b  = (const float*)d_in[3];
    const float* ga         = (const float*)d_in[4];
    const float* gf         = (const float*)d_in[5];
    const float* Wq         = (const float*)d_in[6];
    const float* Wk         = (const float*)d_in[7];
    const float* Wv         = (const float*)d_in[8];
    const float* Wo         = (const float*)d_in[9];
    const float* bo         = (const float*)d_in[10];
    const float* relpos     = (const float*)d_in[11];
    const float* W1         = (const float*)d_in[12];
    const float* b1         = (const float*)d_in[13];
    const float* W2         = (const float*)d_in[14];
    const float* b2         = (const float*)d_in[15];
    const float* ln_g       = (const float*)d_in[16];
    const float* ln_b       = (const float*)d_in[17];
    const float* proj_out_w = (const float*)d_in[18];
    const float* proj_out_b = (const float*)d_in[19];
    const float* cls_w      = (const float*)d_in[20];
    const float* cls_b      = (const float*)d_in[21];
    float* outp = (float*)d_out;

    float *px, *ph, *phn, *pq, *pk, *pv, *po, *pff, *pout, *pwt;
    cudaGetSymbolAddress((void**)&px,  g_x);
    cudaGetSymbolAddress((void**)&ph,  g_h);
    cudaGetSymbolAddress((void**)&phn, g_hn);
    cudaGetSymbolAddress((void**)&pq,  g_q);
    cudaGetSymbolAddress((void**)&pk,  g_k);
    cudaGetSymbolAddress((void**)&pv,  g_v);
    cudaGetSymbolAddress((void**)&po,  g_o);
    cudaGetSymbolAddress((void**)&pff, g_ff);
    cudaGetSymbolAddress((void**)&pout,g_out2);
    cudaGetSymbolAddress((void**)&pwt, g_wt);

    cudaFuncSetAttribute(tgemm_kernel<1,false,0,0>, cudaFuncAttributeMaxDynamicSharedMemorySize, GEMM_SMEM);
    cudaFuncSetAttribute(tgemm_kernel<2,false,0,0>, cudaFuncAttributeMaxDynamicSharedMemorySize, GEMM_SMEM);
    cudaFuncSetAttribute(tgemm_kernel<3,false,1,0>, cudaFuncAttributeMaxDynamicSharedMemorySize, GEMM_SMEM);
    cudaFuncSetAttribute(tgemm_kernel<1,false,2,1>, cudaFuncAttributeMaxDynamicSharedMemorySize, GEMM_SMEM);
    cudaFuncSetAttribute(tgemm_kernel<1,true ,0,0>, cudaFuncAttributeMaxDynamicSharedMemorySize, GEMM_SMEM);
    cudaFuncSetAttribute(qkv_kernel,                cudaFuncAttributeMaxDynamicSharedMemorySize, GEMM_SMEM);
    cudaFuncSetAttribute(flash_attn_kernel,         cudaFuncAttributeMaxDynamicSharedMemorySize, FLASH_SMEM);

    // pre-round all weights to tf32 (single merged launch)
    {
        CvtSrcs cs;
        cs.s[0] = proj_in_w; cs.s[1] = Wq; cs.s[2] = Wk; cs.s[3] = Wv;
        cs.s[4] = Wo; cs.s[5] = W1; cs.s[6] = W2; cs.s[7] = proj_out_w; cs.s[8] = cls_w;
        int n4 = (WT_TOTAL + 3) / 4;
        cvt_all_kernel<<<(n4 + 255)/256, 256>>>(cs, pwt);
    }

    bias_table_kernel<<<4, 256>>>(relpos);
    embed_kernel<<<MTOT, 256>>>(saml, emb_table);

    tgemm_kernel<1,false,0,0><<<gemm_grid(DMODEL), 256, GEMM_SMEM>>>(MTOT, DMODEL, DIN,
        px, DIN, pwt + OFF_PIN, DMODEL, proj_in_b, nullptr, 0, ph, DMODEL, nullptr);

    for (int l = 0; l < 6; l++) {
        const float* wq = pwt + OFF_WQ + (long)l*SZ_W;
        const float* wk = pwt + OFF_WK + (long)l*SZ_W;
        const float* wv = pwt + OFF_WV + (long)l*SZ_W;
        const float* wo = pwt + OFF_WO + (long)l*SZ_W;
        const float* w1 = pwt + OFF_W1 + (long)l*SZ_W1;
        const float* w2 = pwt + OFF_W2 + (long)l*SZ_W1;

        scalenorm_kernel<<<MTOT/8, 256>>>(ph, phn, ga + l);
        qkv_kernel<<<dim3(12, MTOT/128), 256, GEMM_SMEM>>>(phn, wq, wk, wv, pq, pk, pv);
        flash_attn_kernel<<<dim3(SEQ/64, BATCH*NHEADS), 256, FLASH_SMEM>>>(pq, pk, pv, po);
        tgemm_kernel<2,false,0,0><<<gemm_grid(DMODEL), 256, GEMM_SMEM>>>(MTOT, DMODEL, DMODEL,
            po, DMODEL, wo, DMODEL, bo + (long)l*DMODEL, ph, DMODEL, ph, DMODEL, nullptr);
        scalenorm_kernel<<<MTOT/8, 256>>>(ph, phn, gf + l);
        tgemm_kernel<3,false,1,0><<<gemm_grid(DFF), 256, GEMM_SMEM>>>(MTOT, DFF, DMODEL,
            phn, DMODEL, w1, DFF, b1 + (long)l*DFF, nullptr, 0, pff, DFF, nullptr);
        tgemm_kernel<2,false,0,0><<<gemm_grid(DMODEL), 256, GEMM_SMEM>>>(MTOT, DMODEL, DFF,
            pff, DFF, w2, DMODEL, b2 + (long)l*DMODEL, ph, DMODEL, ph, DMODEL, nullptr);
    }

    layernorm_kernel<<<MTOT/8, 256>>>(ph, ln_g, ln_b);
    // out = h @ proj_out_w + b; cols<512 -> g_out2 (rounded), cols>=512 -> d_out tail (exact)
    tgemm_kernel<1,false,2,1><<<gemm_grid(DIN), 256, GEMM_SMEM>>>(MTOT, DIN, DMODEL,
        ph, DMODEL, pwt + OFF_POUT, DIN, proj_out_b, nullptr, 0, pout, DIN, outp);
    // classifier logits, stored transposed into d_out
    tgemm_kernel<1,true,0,0><<<gemm_grid(NCLS), 256, GEMM_SMEM>>>(MTOT, NCLS, DMODEL,
        pout, DIN, pwt + OFF_CLS, NCLS, cls_b, nullptr, 0, outp, 0, nullptr);
}